// round 4
// baseline (speedup 1.0000x reference)
#include <cuda_runtime.h>
#include <math.h>

#define NPTS 16384
#define KNN  16
#define GD   32
#define NCELLS (GD * GD * GD)

// ---------------- scratch (device globals; no allocation allowed) ----------------
__device__ float4 g_pts [NPTS];
__device__ float4 g_spts[NPTS];
__device__ int    g_pcell[NPTS];
__device__ int    g_ssid [NPTS];
__device__ int    g_scell[NPTS];
__device__ int    g_hist [NCELLS];
__device__ int    g_cellstart[NCELLS + 1];
__device__ int    g_cellptr  [NCELLS];
__device__ unsigned g_bbmin[3];
__device__ unsigned g_bbmax[3];
__device__ unsigned g_done;
__device__ float  g_gp[8];     // ox,oy,oz, ix,iy,iz, hmin
__device__ int    g_nbr [NPTS * KNN];
__device__ float  g_qkvs[NPTS * 512];
__device__ float  g_h1 [NPTS * 128];
__device__ float  g_h2 [NPTS * 128];
__device__ float  g_Wp1[64  * 512];
__device__ float  g_Wp2[128 * 512];
__device__ float  g_Wp3[128 * 12];
__device__ float  g_Bp1[512];
__device__ float  g_Bp2[512];
__device__ float  g_Bp3[12];

// monotone float <-> unsigned key (for atomic min/max)
__device__ __forceinline__ unsigned fkey(float f) {
    unsigned u = __float_as_uint(f);
    return (u & 0x80000000u) ? ~u : (u | 0x80000000u);
}
__device__ __forceinline__ float funkey(unsigned u) {
    u = (u & 0x80000000u) ? (u & 0x7fffffffu) : ~u;
    return __uint_as_float(u);
}

// ---------------- 1) bbox over coords; last block computes grid params ----------------
__global__ void bbox_kernel(const float* __restrict__ x) {
    __shared__ float smn[3][8], smx[3][8];
    int tid = threadIdx.x;
    int i = blockIdx.x * 256 + tid;          // 64 blocks x 256 = 16384
    float v[3];
    v[0] = x[i * 64 + 0]; v[1] = x[i * 64 + 1]; v[2] = x[i * 64 + 2];
    float mn[3] = {v[0], v[1], v[2]}, mx[3] = {v[0], v[1], v[2]};
#pragma unroll
    for (int o = 16; o > 0; o >>= 1)
#pragma unroll
        for (int d = 0; d < 3; d++) {
            mn[d] = fminf(mn[d], __shfl_xor_sync(0xffffffffu, mn[d], o));
            mx[d] = fmaxf(mx[d], __shfl_xor_sync(0xffffffffu, mx[d], o));
        }
    int w = tid >> 5, l = tid & 31;
    if (l == 0)
#pragma unroll
        for (int d = 0; d < 3; d++) { smn[d][w] = mn[d]; smx[d][w] = mx[d]; }
    __syncthreads();
    if (tid == 0) {
#pragma unroll
        for (int d = 0; d < 3; d++) {
            float a = smn[d][0], b = smx[d][0];
            for (int ww = 1; ww < 8; ww++) {
                a = fminf(a, smn[d][ww]); b = fmaxf(b, smx[d][ww]);
            }
            atomicMin(&g_bbmin[d], fkey(a));
            atomicMax(&g_bbmax[d], fkey(b));
        }
        __threadfence();
        if (atomicAdd(&g_done, 1u) == 63u) {
            float hmin = 1e30f;
            for (int d = 0; d < 3; d++) {
                float lo = funkey(atomicAdd(&g_bbmin[d], 0u)) - 1e-4f;
                float hi = funkey(atomicAdd(&g_bbmax[d], 0u)) + 1e-4f;
                float h = (hi - lo) / (float)GD;
                g_gp[d] = lo;
                g_gp[3 + d] = (float)GD / (hi - lo);
                hmin = fminf(hmin, h);
            }
            g_gp[6] = hmin;
        }
    }
}

// ---------------- 2) pack coords + |p|^2, cell assignment, histogram ----------------
__global__ void prep_hist_kernel(const float* __restrict__ x) {
    int i = blockIdx.x * blockDim.x + threadIdx.x;
    if (i >= NPTS) return;
    float a = x[i * 64 + 0], b = x[i * 64 + 1], c = x[i * 64 + 2];
    g_pts[i] = make_float4(a, b, c, a * a + b * b + c * c);
    int cx = min(max((int)((a - g_gp[0]) * g_gp[3]), 0), GD - 1);
    int cy = min(max((int)((b - g_gp[1]) * g_gp[4]), 0), GD - 1);
    int cz = min(max((int)((c - g_gp[2]) * g_gp[5]), 0), GD - 1);
    int cell = (cz << 10) | (cy << 5) | cx;
    g_pcell[i] = cell;
    atomicAdd(&g_hist[cell], 1);
}

// ---------------- 3) single-block scan of 32768 cells + scatter ----------------
__global__ void __launch_bounds__(1024) scan_scatter_kernel() {
    __shared__ int sm[1024];
    int tid = threadIdx.x;
    int base = tid * (NCELLS / 1024);        // 32 cells per thread
    int s = 0;
    for (int j = 0; j < NCELLS / 1024; j++) s += g_hist[base + j];
    sm[tid] = s;
    __syncthreads();
    for (int off = 1; off < 1024; off <<= 1) {
        int v = (tid >= off) ? sm[tid - off] : 0;
        __syncthreads();
        sm[tid] += v;
        __syncthreads();
    }
    int run = sm[tid] - s;                   // exclusive
    for (int j = 0; j < NCELLS / 1024; j++) {
        g_cellstart[base + j] = run;
        g_cellptr[base + j] = run;
        run += g_hist[base + j];
    }
    if (tid == 1023) g_cellstart[NCELLS] = run;
    __syncthreads();
    for (int i = tid; i < NPTS; i += 1024) {
        int c = g_pcell[i];
        int slot = atomicAdd(&g_cellptr[c], 1);
        g_spts[slot] = g_pts[i];
        g_ssid[slot] = i;
        g_scell[slot] = c;
    }
}

// stable ascending insert of (d, j) into 16-deep register list
__device__ __forceinline__ void insert16(float (&dist)[KNN], int (&idx)[KNN],
                                         float d, int j) {
#pragma unroll
    for (int s = KNN - 1; s >= 0; --s) {
        float cur = dist[s];
        if (d < cur) {
            bool ins = (s == 0) || (d >= dist[s - 1]);
            dist[s] = ins ? d : dist[s - 1];
            idx [s] = ins ? j : idx [s - 1];
        }
    }
}

__device__ __forceinline__ void scan_range(int s0, int s1, int self,
                                           float nx, float ny, float nz,
                                           float (&dist)[KNN], int (&idx)[KNN]) {
    for (int s = s0; s < s1; s++) {
        float4 q = g_spts[s];
        float d = fmaf(nx, q.x, fmaf(ny, q.y, fmaf(nz, q.z, q.w)));
        if (d < dist[KNN - 1] && s != self) {
            insert16(dist, idx, d, g_ssid[s]);
        }
    }
}

// ---------------- 4) exact kNN query via expanding Chebyshev rings ----------------
__global__ void __launch_bounds__(128) knn_query_kernel() {
    int t = blockIdx.x * 128 + threadIdx.x;      // sorted-order query slot
    float4 p = g_spts[t];
    int myid = g_ssid[t];
    int cc = g_scell[t];
    int cx = cc & (GD - 1), cy = (cc >> 5) & (GD - 1), cz = cc >> 10;
    float nx = -2.f * p.x, ny = -2.f * p.y, nz = -2.f * p.z;
    float hmin = g_gp[6];

    float dist[KNN];
    int   idx [KNN];
#pragma unroll
    for (int u = 0; u < KNN; u++) { dist[u] = __int_as_float(0x7f800000); idx[u] = 0; }

    for (int r = 0; r < GD; r++) {
        if (r > 0) {
            float b = (float)(r - 1) * hmin;
            float kt = dist[KNN - 1] + p.w;      // ~ true squared distance of kth
            if (kt * 1.0001f <= b * b) break;    // conservative: inflate kt
        }
        if (r == 0) {
            scan_range(g_cellstart[cc], g_cellstart[cc + 1], t, nx, ny, nz, dist, idx);
        } else {
            for (int dz = -r; dz <= r; dz++) {
                int z = cz + dz;
                if ((unsigned)z >= GD) continue;
                int zb = z << 10;
                bool zface = (dz == -r) | (dz == r);
                for (int dy = -r; dy <= r; dy++) {
                    int y = cy + dy;
                    if ((unsigned)y >= GD) continue;
                    int rowb = zb | (y << 5);
                    if (zface | (dy == -r) | (dy == r)) {
                        // full x-run: cells contiguous in CSR -> one merged range
                        int x0 = max(cx - r, 0), x1 = min(cx + r, GD - 1);
                        scan_range(g_cellstart[rowb + x0], g_cellstart[rowb + x1 + 1],
                                   t, nx, ny, nz, dist, idx);
                    } else {
                        int xl = cx - r;
                        if (xl >= 0)
                            scan_range(g_cellstart[rowb + xl], g_cellstart[rowb + xl + 1],
                                       t, nx, ny, nz, dist, idx);
                        int xr = cx + r;
                        if (xr < GD)
                            scan_range(g_cellstart[rowb + xr], g_cellstart[rowb + xr + 1],
                                       t, nx, ny, nz, dist, idx);
                    }
                }
            }
        }
    }
#pragma unroll
    for (int u = 0; u < KNN; u++) g_nbr[myid * KNN + u] = idx[u];
}

// ---------------- weight / bias packing ----------------
__global__ void pack_w_kernel(const float* __restrict__ a, const float* __restrict__ b,
                              const float* __restrict__ c, const float* __restrict__ d,
                              float* __restrict__ dst, int D, int Pp) {
    int i = blockIdx.x * blockDim.x + threadIdx.x;
    if (i >= D * Pp) return;
    int r = i / Pp, col = i - r * Pp;
    float* o = dst + (size_t)r * 4 * Pp + col;
    o[0 * Pp] = a[i]; o[1 * Pp] = b[i]; o[2 * Pp] = c[i]; o[3 * Pp] = d[i];
}

__global__ void pack_b_kernel(const float* __restrict__ a, const float* __restrict__ b,
                              const float* __restrict__ c, const float* __restrict__ d,
                              float* __restrict__ dst, int Pp) {
    int i = blockIdx.x * blockDim.x + threadIdx.x;
    if (i >= Pp) return;
    dst[i] = a[i]; dst[Pp + i] = b[i]; dst[2 * Pp + i] = c[i]; dst[3 * Pp + i] = d[i];
}

// ---------------- big SGEMM: C[N,P] = X[N,D] @ W[D,P] + bias ----------------
#define GBM 128
#define GBN 128
#define GBK 16
__global__ void __launch_bounds__(256)
gemm128_kernel(const float* __restrict__ X, const float* __restrict__ W,
               const float* __restrict__ bias, float* __restrict__ C,
               int D, int P) {
    __shared__ float As[GBK][GBM];
    __shared__ float Bs[GBK][GBN];
    int tid = threadIdx.x;
    int bm = blockIdx.x * GBM;
    int bn = blockIdx.y * GBN;

    int ar = tid >> 1;
    int ak = (tid & 1) << 3;
    int bk = tid >> 5;
    int bc = (tid & 31) << 2;
    int tr = tid >> 4, tc = tid & 15;

    const float* xr = X + (size_t)(bm + ar) * D + ak;
    float acc[8][8] = {};

    for (int k0 = 0; k0 < D; k0 += GBK) {
        float4 a0 = *(const float4*)(xr + k0);
        float4 a1 = *(const float4*)(xr + k0 + 4);
        As[ak + 0][ar] = a0.x; As[ak + 1][ar] = a0.y;
        As[ak + 2][ar] = a0.z; As[ak + 3][ar] = a0.w;
        As[ak + 4][ar] = a1.x; As[ak + 5][ar] = a1.y;
        As[ak + 6][ar] = a1.z; As[ak + 7][ar] = a1.w;
        *(float4*)&Bs[bk][bc] =
            *(const float4*)(W + (size_t)(k0 + bk) * P + bn + bc);
        *(float4*)&Bs[bk + 8][bc] =
            *(const float4*)(W + (size_t)(k0 + bk + 8) * P + bn + bc);
        __syncthreads();
#pragma unroll
        for (int kk = 0; kk < GBK; kk++) {
            float4 av0 = *(const float4*)&As[kk][tr * 8];
            float4 av1 = *(const float4*)&As[kk][tr * 8 + 4];
            float4 bv0 = *(const float4*)&Bs[kk][tc * 8];
            float4 bv1 = *(const float4*)&Bs[kk][tc * 8 + 4];
            float a[8] = {av0.x, av0.y, av0.z, av0.w, av1.x, av1.y, av1.z, av1.w};
            float bb[8] = {bv0.x, bv0.y, bv0.z, bv0.w, bv1.x, bv1.y, bv1.z, bv1.w};
#pragma unroll
            for (int i = 0; i < 8; i++)
#pragma unroll
                for (int j = 0; j < 8; j++)
                    acc[i][j] = fmaf(a[i], bb[j], acc[i][j]);
        }
        __syncthreads();
    }

    float bb0[8];
#pragma unroll
    for (int j = 0; j < 8; j++) bb0[j] = bias[bn + tc * 8 + j];
#pragma unroll
    for (int i = 0; i < 8; i++) {
        size_t row = bm + tr * 8 + i;
        float4 o0 = make_float4(acc[i][0] + bb0[0], acc[i][1] + bb0[1],
                                acc[i][2] + bb0[2], acc[i][3] + bb0[3]);
        float4 o1 = make_float4(acc[i][4] + bb0[4], acc[i][5] + bb0[5],
                                acc[i][6] + bb0[6], acc[i][7] + bb0[7]);
        *(float4*)(C + row * P + bn + tc * 8)     = o0;
        *(float4*)(C + row * P + bn + tc * 8 + 4) = o1;
    }
}

// ---------------- small SGEMM (layer 3, P=12), bounds-checked ----------------
#define BM 64
#define BN 64
#define BKT 16
__global__ void gemm_kernel(const float* __restrict__ X, const float* __restrict__ W,
                            const float* __restrict__ bias, float* __restrict__ C,
                            int D, int P) {
    __shared__ float As[BKT][BM];
    __shared__ float Bs[BKT][BN];
    int bm = blockIdx.x * BM;
    int bn = blockIdx.y * BN;
    int tid = threadIdx.x;
    int tr = tid >> 4, tc = tid & 15;
    float acc[4][4] = {};

    for (int k0 = 0; k0 < D; k0 += BKT) {
        for (int t = tid; t < BM * BKT; t += 256) {
            int m = t >> 4, k = t & 15;
            As[k][m] = X[(size_t)(bm + m) * D + k0 + k];
        }
        for (int t = tid; t < BKT * BN; t += 256) {
            int k = t >> 6, n = t & 63;
            int nn = bn + n;
            Bs[k][n] = (nn < P) ? W[(size_t)(k0 + k) * P + nn] : 0.f;
        }
        __syncthreads();
#pragma unroll
        for (int kk = 0; kk < BKT; kk++) {
            float4 av = *(const float4*)&As[kk][tr * 4];
            float4 bv = *(const float4*)&Bs[kk][tc * 4];
            float a[4] = {av.x, av.y, av.z, av.w};
            float bb[4] = {bv.x, bv.y, bv.z, bv.w};
#pragma unroll
            for (int i = 0; i < 4; i++)
#pragma unroll
                for (int j = 0; j < 4; j++)
                    acc[i][j] = fmaf(a[i], bb[j], acc[i][j]);
        }
        __syncthreads();
    }
#pragma unroll
    for (int i = 0; i < 4; i++) {
        int row = bm + tr * 4 + i;
#pragma unroll
        for (int j = 0; j < 4; j++) {
            int col = bn + tc * 4 + j;
            if (col < P) C[(size_t)row * P + col] = acc[i][j] + bias[col];
        }
    }
}

// ---------------- attention, c=128 layers (block per node); packed QKVS ----------------
__global__ void attn128_kernel(const float* __restrict__ pk,
                               const float* __restrict__ resid,
                               float* __restrict__ outp, int do_tanh) {
    __shared__ float sq[128];
    __shared__ float al[16];
    __shared__ int   nb[16];
    int i = blockIdx.x;
    int t = threadIdx.x;
    if (t < 16) nb[t] = g_nbr[i * 16 + t];
    sq[t] = pk[(size_t)i * 512 + t];            // Q at offset 0
    __syncthreads();

    int w = t >> 5, l = t & 31;
#pragma unroll
    for (int ee = 0; ee < 4; ee++) {
        int e = (w << 2) + ee;
        int j = nb[e];
        const float* kj = pk + (size_t)j * 512 + 128;   // K at offset 128
        float a = sq[l] * kj[l];
        a = fmaf(sq[l + 32], kj[l + 32], a);
        a = fmaf(sq[l + 64], kj[l + 64], a);
        a = fmaf(sq[l + 96], kj[l + 96], a);
#pragma unroll
        for (int o = 16; o > 0; o >>= 1) a += __shfl_xor_sync(0xffffffffu, a, o);
        if (l == 0) al[e] = a * 0.08838834764831845f;   // 1/sqrt(128)
    }
    __syncthreads();
    if (t < 32) {
        float a = (l < 16) ? al[l] : -__int_as_float(0x7f800000);
        float m = a;
#pragma unroll
        for (int o = 16; o > 0; o >>= 1) m = fmaxf(m, __shfl_xor_sync(0xffffffffu, m, o));
        float ex = (l < 16) ? expf(a - m) : 0.f;
        float sm = ex;
#pragma unroll
        for (int o = 16; o > 0; o >>= 1) sm += __shfl_xor_sync(0xffffffffu, sm, o);
        if (l < 16) al[l] = ex / sm;
    }
    __syncthreads();

    float acc = pk[(size_t)i * 512 + 384 + t];          // S at offset 384
#pragma unroll
    for (int e = 0; e < 16; e++)
        acc = fmaf(al[e], pk[(size_t)nb[e] * 512 + 256 + t], acc);  // V at 256
    if (resid) acc += resid[(size_t)i * 128 + t];
    outp[(size_t)i * 128 + t] = do_tanh ? tanhf(acc) : acc;
}

// ---------------- attention, c=3 final layer (warp per node); packed P=12 ----------------
__global__ void attn3_kernel(const float* __restrict__ pk, float* __restrict__ outp) {
    int gt = blockIdx.x * blockDim.x + threadIdx.x;
    int i = gt >> 5;
    int l = gt & 31;
    if (i >= NPTS) return;
    int j = 0;
    float a = -__int_as_float(0x7f800000);
    if (l < 16) {
        j = g_nbr[i * 16 + l];
        float qx = pk[i * 12 + 0], qy = pk[i * 12 + 1], qz = pk[i * 12 + 2];
        a = fmaf(qx, pk[j * 12 + 3], fmaf(qy, pk[j * 12 + 4], qz * pk[j * 12 + 5]))
            * 0.5773502691896258f;   // 1/sqrt(3)
    }
    float m = a;
#pragma unroll
    for (int o = 16; o > 0; o >>= 1) m = fmaxf(m, __shfl_xor_sync(0xffffffffu, m, o));
    float ex = (l < 16) ? expf(a - m) : 0.f;
    float sm = ex;
#pragma unroll
    for (int o = 16; o > 0; o >>= 1) sm += __shfl_xor_sync(0xffffffffu, sm, o);
    float wgt = ex / sm;
    float vx = 0.f, vy = 0.f, vz = 0.f;
    if (l < 16) {
        vx = wgt * pk[j * 12 + 6];
        vy = wgt * pk[j * 12 + 7];
        vz = wgt * pk[j * 12 + 8];
    }
#pragma unroll
    for (int o = 16; o > 0; o >>= 1) {
        vx += __shfl_xor_sync(0xffffffffu, vx, o);
        vy += __shfl_xor_sync(0xffffffffu, vy, o);
        vz += __shfl_xor_sync(0xffffffffu, vz, o);
    }
    if (l == 0) {
        outp[i * 3 + 0] = vx + pk[i * 12 + 9];
        outp[i * 3 + 1] = vy + pk[i * 12 + 10];
        outp[i * 3 + 2] = vz + pk[i * 12 + 11];
    }
}

// ---------------- host ----------------
extern "C" void kernel_launch(void* const* d_in, const int* in_sizes, int n_in,
                              void* d_out, int out_size) {
    const float* x = (const float*)d_in[1];
    const float* W1[4] = {(const float*)d_in[2], (const float*)d_in[4],
                          (const float*)d_in[6], (const float*)d_in[8]};
    const float* B1[4] = {(const float*)d_in[3], (const float*)d_in[5],
                          (const float*)d_in[7], (const float*)d_in[9]};
    const float* W2[4] = {(const float*)d_in[10], (const float*)d_in[12],
                          (const float*)d_in[14], (const float*)d_in[16]};
    const float* B2[4] = {(const float*)d_in[11], (const float*)d_in[13],
                          (const float*)d_in[15], (const float*)d_in[17]};
    const float* W3[4] = {(const float*)d_in[18], (const float*)d_in[20],
                          (const float*)d_in[22], (const float*)d_in[24]};
    const float* B3[4] = {(const float*)d_in[19], (const float*)d_in[21],
                          (const float*)d_in[23], (const float*)d_in[25]};
    float* out = (float*)d_out;

    float *qkvs, *h1, *h2, *Wp1, *Wp2, *Wp3, *Bp1, *Bp2, *Bp3;
    void *hist, *bbmin, *bbmax, *done;
    cudaGetSymbolAddress((void**)&qkvs, g_qkvs);
    cudaGetSymbolAddress((void**)&h1,  g_h1);
    cudaGetSymbolAddress((void**)&h2,  g_h2);
    cudaGetSymbolAddress((void**)&Wp1, g_Wp1);
    cudaGetSymbolAddress((void**)&Wp2, g_Wp2);
    cudaGetSymbolAddress((void**)&Wp3, g_Wp3);
    cudaGetSymbolAddress((void**)&Bp1, g_Bp1);
    cudaGetSymbolAddress((void**)&Bp2, g_Bp2);
    cudaGetSymbolAddress((void**)&Bp3, g_Bp3);
    cudaGetSymbolAddress(&hist,  g_hist);
    cudaGetSymbolAddress(&bbmin, g_bbmin);
    cudaGetSymbolAddress(&bbmax, g_bbmax);
    cudaGetSymbolAddress(&done,  g_done);

    // per-replay state reset (stream memsets, graph-capturable, not kernels)
    cudaMemsetAsync(hist,  0x00, NCELLS * sizeof(int));
    cudaMemsetAsync(bbmin, 0xFF, 3 * sizeof(unsigned));
    cudaMemsetAsync(bbmax, 0x00, 3 * sizeof(unsigned));
    cudaMemsetAsync(done,  0x00, sizeof(unsigned));

    // grid-kNN pipeline: query kernel is the 4th kernel launch (ncu capture slot)
    bbox_kernel<<<64, 256>>>(x);                 // 1
    prep_hist_kernel<<<64, 256>>>(x);            // 2
    scan_scatter_kernel<<<1, 1024>>>();          // 3
    knn_query_kernel<<<NPTS / 128, 128>>>();     // 4 <- profiled

    pack_b_kernel<<<1, 128>>>(B1[0], B1[1], B1[2], B1[3], Bp1, 128);
    pack_b_kernel<<<1, 128>>>(B2[0], B2[1], B2[2], B2[3], Bp2, 128);
    pack_b_kernel<<<1, 128>>>(B3[0], B3[1], B3[2], B3[3], Bp3, 3);
    pack_w_kernel<<<(64 * 128 + 255) / 256, 256>>>(W1[0], W1[1], W1[2], W1[3], Wp1, 64, 128);
    pack_w_kernel<<<(128 * 128 + 255) / 256, 256>>>(W2[0], W2[1], W2[2], W2[3], Wp2, 128, 128);
    pack_w_kernel<<<(128 * 3 + 255) / 256, 256>>>(W3[0], W3[1], W3[2], W3[3], Wp3, 128, 3);

    // layer 1
    {
        dim3 grid(NPTS / GBM, 512 / GBN);
        gemm128_kernel<<<grid, 256>>>(x, Wp1, Bp1, qkvs, 64, 512);
    }
    attn128_kernel<<<NPTS, 128>>>(qkvs, nullptr, h1, 1);

    // layer 2
    {
        dim3 grid(NPTS / GBM, 512 / GBN);
        gemm128_kernel<<<grid, 256>>>(h1, Wp2, Bp2, qkvs, 128, 512);
    }
    attn128_kernel<<<NPTS, 128>>>(qkvs, h1, h2, 1);

    // layer 3
    {
        dim3 grid(NPTS / BM, 1);
        gemm_kernel<<<grid, 256>>>(h2, Wp3, Bp3, qkvs, 128, 12);
    }
    attn3_kernel<<<(NPTS * 32) / 128, 128>>>(qkvs, out);
}

// round 5
// speedup vs baseline: 1.0290x; 1.0290x over previous
#include <cuda_runtime.h>
#include <math.h>

#define NPTS 16384
#define KNN  16
#define GD   32
#define NCELLS (GD * GD * GD)

// ---------------- scratch (device globals; no allocation allowed) ----------------
__device__ float4 g_pts [NPTS];
__device__ float4 g_spts[NPTS];
__device__ int    g_pcell[NPTS];
__device__ int    g_ssid [NPTS];
__device__ int    g_scell[NPTS];
__device__ int    g_hist [NCELLS];
__device__ int    g_cellstart[NCELLS + 1];
__device__ int    g_cellptr  [NCELLS];
__device__ unsigned g_bbmin[3];
__device__ unsigned g_bbmax[3];
__device__ unsigned g_done;
__device__ float  g_gp[8];     // ox,oy,oz, ix,iy,iz, hmin
__device__ int    g_nbr [NPTS * KNN];
__device__ float  g_qkvs[NPTS * 512];
__device__ float  g_h1 [NPTS * 128];
__device__ float  g_h2 [NPTS * 128];
__device__ float  g_Wp1[64  * 512];
__device__ float  g_Wp2[128 * 512];
__device__ float  g_Wp3[128 * 12];
__device__ float  g_Bp1[512];
__device__ float  g_Bp2[512];
__device__ float  g_Bp3[12];

// monotone float <-> unsigned key (for atomic min/max and sort keys)
__device__ __forceinline__ unsigned fkey(float f) {
    unsigned u = __float_as_uint(f);
    return (u & 0x80000000u) ? ~u : (u | 0x80000000u);
}
__device__ __forceinline__ float funkey(unsigned u) {
    u = (u & 0x80000000u) ? (u & 0x7fffffffu) : ~u;
    return __uint_as_float(u);
}

// ---------------- bbox over coords; last block computes grid params ----------------
__global__ void bbox_kernel(const float* __restrict__ x) {
    __shared__ float smn[3][8], smx[3][8];
    int tid = threadIdx.x;
    int i = blockIdx.x * 256 + tid;          // 64 blocks x 256 = 16384
    float v[3];
    v[0] = x[i * 64 + 0]; v[1] = x[i * 64 + 1]; v[2] = x[i * 64 + 2];
    float mn[3] = {v[0], v[1], v[2]}, mx[3] = {v[0], v[1], v[2]};
#pragma unroll
    for (int o = 16; o > 0; o >>= 1)
#pragma unroll
        for (int d = 0; d < 3; d++) {
            mn[d] = fminf(mn[d], __shfl_xor_sync(0xffffffffu, mn[d], o));
            mx[d] = fmaxf(mx[d], __shfl_xor_sync(0xffffffffu, mx[d], o));
        }
    int w = tid >> 5, l = tid & 31;
    if (l == 0)
#pragma unroll
        for (int d = 0; d < 3; d++) { smn[d][w] = mn[d]; smx[d][w] = mx[d]; }
    __syncthreads();
    if (tid == 0) {
#pragma unroll
        for (int d = 0; d < 3; d++) {
            float a = smn[d][0], b = smx[d][0];
            for (int ww = 1; ww < 8; ww++) {
                a = fminf(a, smn[d][ww]); b = fmaxf(b, smx[d][ww]);
            }
            atomicMin(&g_bbmin[d], fkey(a));
            atomicMax(&g_bbmax[d], fkey(b));
        }
        __threadfence();
        if (atomicAdd(&g_done, 1u) == 63u) {
            float hmin = 1e30f;
            for (int d = 0; d < 3; d++) {
                float lo = funkey(atomicAdd(&g_bbmin[d], 0u)) - 1e-4f;
                float hi = funkey(atomicAdd(&g_bbmax[d], 0u)) + 1e-4f;
                float h = (hi - lo) / (float)GD;
                g_gp[d] = lo;
                g_gp[3 + d] = (float)GD / (hi - lo);
                hmin = fminf(hmin, h);
            }
            g_gp[6] = hmin;
        }
    }
}

// ---------------- pack coords + |p|^2, cell assignment, histogram ----------------
__global__ void prep_hist_kernel(const float* __restrict__ x) {
    int i = blockIdx.x * blockDim.x + threadIdx.x;
    if (i >= NPTS) return;
    float a = x[i * 64 + 0], b = x[i * 64 + 1], c = x[i * 64 + 2];
    g_pts[i] = make_float4(a, b, c, a * a + b * b + c * c);
    int cx = min(max((int)((a - g_gp[0]) * g_gp[3]), 0), GD - 1);
    int cy = min(max((int)((b - g_gp[1]) * g_gp[4]), 0), GD - 1);
    int cz = min(max((int)((c - g_gp[2]) * g_gp[5]), 0), GD - 1);
    int cell = (cz << 10) | (cy << 5) | cx;
    g_pcell[i] = cell;
    atomicAdd(&g_hist[cell], 1);
}

// ---------------- single-block scan of 32768 cells + scatter ----------------
__global__ void __launch_bounds__(1024) scan_scatter_kernel() {
    __shared__ int sm[1024];
    int tid = threadIdx.x;
    int base = tid * (NCELLS / 1024);        // 32 cells per thread
    int s = 0;
    for (int j = 0; j < NCELLS / 1024; j++) s += g_hist[base + j];
    sm[tid] = s;
    __syncthreads();
    for (int off = 1; off < 1024; off <<= 1) {
        int v = (tid >= off) ? sm[tid - off] : 0;
        __syncthreads();
        sm[tid] += v;
        __syncthreads();
    }
    int run = sm[tid] - s;                   // exclusive
    for (int j = 0; j < NCELLS / 1024; j++) {
        g_cellstart[base + j] = run;
        g_cellptr[base + j] = run;
        run += g_hist[base + j];
    }
    if (tid == 1023) g_cellstart[NCELLS] = run;
    __syncthreads();
    for (int i = tid; i < NPTS; i += 1024) {
        int c = g_pcell[i];
        int slot = atomicAdd(&g_cellptr[c], 1);
        g_spts[slot] = g_pts[i];
        g_ssid[slot] = i;
        g_scell[slot] = c;
    }
}

// stable ascending insert of (d, j) into 16-deep register list
__device__ __forceinline__ void insert16(float (&dist)[KNN], int (&idx)[KNN],
                                         float d, int j) {
#pragma unroll
    for (int s = KNN - 1; s >= 0; --s) {
        float cur = dist[s];
        if (d < cur) {
            bool ins = (s == 0) || (d >= dist[s - 1]);
            dist[s] = ins ? d : dist[s - 1];
            idx [s] = ins ? j : idx [s - 1];
        }
    }
}

// warp-cooperative scan of a contiguous sorted-point range (lane-strided)
__device__ __forceinline__ void scan_range_w(int s0, int s1, int lane, int self,
                                             float nx, float ny, float nz,
                                             float (&dist)[KNN], int (&idx)[KNN]) {
    for (int s = s0 + lane; s < s1; s += 32) {
        float4 q = g_spts[s];
        float d = fmaf(nx, q.x, fmaf(ny, q.y, fmaf(nz, q.z, q.w)));
        if (d < dist[KNN - 1] && s != self) {
            insert16(dist, idx, d, g_ssid[s]);
        }
    }
}

// ---------------- exact kNN: one WARP per query, expanding Chebyshev rings ----------------
__global__ void __launch_bounds__(128) knn_query_kernel() {
    int t    = blockIdx.x * 4 + (threadIdx.x >> 5);   // query = sorted slot, one warp each
    int lane = threadIdx.x & 31;
    float4 p = g_spts[t];
    int myid = g_ssid[t];
    int cc   = g_scell[t];
    int cx = cc & (GD - 1), cy = (cc >> 5) & (GD - 1), cz = cc >> 10;
    float nx = -2.f * p.x, ny = -2.f * p.y, nz = -2.f * p.z;
    float hmin = g_gp[6];

    float dist[KNN];
    int   idx [KNN];
#pragma unroll
    for (int u = 0; u < KNN; u++) { dist[u] = __int_as_float(0x7f800000); idx[u] = 0x7fffffff; }

    for (int R = 1; R < GD; R++) {
        if (R == 1) {
            // full cube radius 1 (rings 0+1)
            int z0 = max(cz - 1, 0), z1 = min(cz + 1, GD - 1);
            int y0 = max(cy - 1, 0), y1 = min(cy + 1, GD - 1);
            int x0 = max(cx - 1, 0), x1 = min(cx + 1, GD - 1);
            for (int z = z0; z <= z1; z++)
                for (int y = y0; y <= y1; y++) {
                    int rowb = (z << 10) | (y << 5);
                    scan_range_w(g_cellstart[rowb + x0], g_cellstart[rowb + x1 + 1],
                                 lane, t, nx, ny, nz, dist, idx);
                }
        } else {
            // shell at Chebyshev radius exactly R
            for (int dz = -R; dz <= R; dz++) {
                int z = cz + dz;
                if ((unsigned)z >= GD) continue;
                int zb = z << 10;
                bool zface = (dz == -R) | (dz == R);
                for (int dy = -R; dy <= R; dy++) {
                    int y = cy + dy;
                    if ((unsigned)y >= GD) continue;
                    int rowb = zb | (y << 5);
                    if (zface | (dy == -R) | (dy == R)) {
                        int x0 = max(cx - R, 0), x1 = min(cx + R, GD - 1);
                        scan_range_w(g_cellstart[rowb + x0], g_cellstart[rowb + x1 + 1],
                                     lane, t, nx, ny, nz, dist, idx);
                    } else {
                        int xl = cx - R;
                        if (xl >= 0)
                            scan_range_w(g_cellstart[rowb + xl], g_cellstart[rowb + xl + 1],
                                         lane, t, nx, ny, nz, dist, idx);
                        int xr = cx + R;
                        if (xr < GD)
                            scan_range_w(g_cellstart[rowb + xr], g_cellstart[rowb + xr + 1],
                                         lane, t, nx, ny, nz, dist, idx);
                    }
                }
            }
        }
        // safe stop: warp-min of per-lane kth is an upper bound on the true kth
        float ub = dist[KNN - 1];
#pragma unroll
        for (int o = 16; o > 0; o >>= 1)
            ub = fminf(ub, __shfl_xor_sync(0xffffffffu, ub, o));
        float kt = ub + p.w;                 // ~true squared distance of kth
        float b = (float)R * hmin;           // unscanned points are >= R*hmin away
        if (kt * 1.0001f <= b * b) break;
    }

    // merge 32 sorted per-lane lists: 16 rounds of warp-argmin on (fkey(d), id)
    unsigned out_id = 0;
#pragma unroll
    for (int u = 0; u < KNN; u++) {
        unsigned long long key =
            ((unsigned long long)fkey(dist[0]) << 32) | (unsigned)idx[0];
        unsigned long long m = key;
#pragma unroll
        for (int o = 16; o > 0; o >>= 1) {
            unsigned long long other = __shfl_xor_sync(0xffffffffu, m, o);
            m = (other < m) ? other : m;
        }
        if (key == m) {                      // unique winner (ids distinct): pop head
#pragma unroll
            for (int s2 = 0; s2 < KNN - 1; s2++) {
                dist[s2] = dist[s2 + 1]; idx[s2] = idx[s2 + 1];
            }
            dist[KNN - 1] = __int_as_float(0x7f800000);
            idx [KNN - 1] = 0x7fffffff;
        }
        if (lane == u) out_id = (unsigned)(m & 0xffffffffu);
    }
    if (lane < KNN) g_nbr[myid * KNN + lane] = (int)out_id;
}

// ---------------- weight / bias packing ----------------
__global__ void pack_w_kernel(const float* __restrict__ a, const float* __restrict__ b,
                              const float* __restrict__ c, const float* __restrict__ d,
                              float* __restrict__ dst, int D, int Pp) {
    int i = blockIdx.x * blockDim.x + threadIdx.x;
    if (i >= D * Pp) return;
    int r = i / Pp, col = i - r * Pp;
    float* o = dst + (size_t)r * 4 * Pp + col;
    o[0 * Pp] = a[i]; o[1 * Pp] = b[i]; o[2 * Pp] = c[i]; o[3 * Pp] = d[i];
}

__global__ void pack_b_kernel(const float* __restrict__ a, const float* __restrict__ b,
                              const float* __restrict__ c, const float* __restrict__ d,
                              float* __restrict__ dst, int Pp) {
    int i = blockIdx.x * blockDim.x + threadIdx.x;
    if (i >= Pp) return;
    dst[i] = a[i]; dst[Pp + i] = b[i]; dst[2 * Pp + i] = c[i]; dst[3 * Pp + i] = d[i];
}

// ---------------- big SGEMM: C[N,P] = X[N,D] @ W[D,P] + bias ----------------
#define GBM 128
#define GBN 128
#define GBK 16
__global__ void __launch_bounds__(256)
gemm128_kernel(const float* __restrict__ X, const float* __restrict__ W,
               const float* __restrict__ bias, float* __restrict__ C,
               int D, int P) {
    __shared__ float As[GBK][GBM];
    __shared__ float Bs[GBK][GBN];
    int tid = threadIdx.x;
    int bm = blockIdx.x * GBM;
    int bn = blockIdx.y * GBN;

    int ar = tid >> 1;
    int ak = (tid & 1) << 3;
    int bk = tid >> 5;
    int bc = (tid & 31) << 2;
    int tr = tid >> 4, tc = tid & 15;

    const float* xr = X + (size_t)(bm + ar) * D + ak;
    float acc[8][8] = {};

    for (int k0 = 0; k0 < D; k0 += GBK) {
        float4 a0 = *(const float4*)(xr + k0);
        float4 a1 = *(const float4*)(xr + k0 + 4);
        As[ak + 0][ar] = a0.x; As[ak + 1][ar] = a0.y;
        As[ak + 2][ar] = a0.z; As[ak + 3][ar] = a0.w;
        As[ak + 4][ar] = a1.x; As[ak + 5][ar] = a1.y;
        As[ak + 6][ar] = a1.z; As[ak + 7][ar] = a1.w;
        *(float4*)&Bs[bk][bc] =
            *(const float4*)(W + (size_t)(k0 + bk) * P + bn + bc);
        *(float4*)&Bs[bk + 8][bc] =
            *(const float4*)(W + (size_t)(k0 + bk + 8) * P + bn + bc);
        __syncthreads();
#pragma unroll
        for (int kk = 0; kk < GBK; kk++) {
            float4 av0 = *(const float4*)&As[kk][tr * 8];
            float4 av1 = *(const float4*)&As[kk][tr * 8 + 4];
            float4 bv0 = *(const float4*)&Bs[kk][tc * 8];
            float4 bv1 = *(const float4*)&Bs[kk][tc * 8 + 4];
            float a[8] = {av0.x, av0.y, av0.z, av0.w, av1.x, av1.y, av1.z, av1.w};
            float bb[8] = {bv0.x, bv0.y, bv0.z, bv0.w, bv1.x, bv1.y, bv1.z, bv1.w};
#pragma unroll
            for (int i = 0; i < 8; i++)
#pragma unroll
                for (int j = 0; j < 8; j++)
                    acc[i][j] = fmaf(a[i], bb[j], acc[i][j]);
        }
        __syncthreads();
    }

    float bb0[8];
#pragma unroll
    for (int j = 0; j < 8; j++) bb0[j] = bias[bn + tc * 8 + j];
#pragma unroll
    for (int i = 0; i < 8; i++) {
        size_t row = bm + tr * 8 + i;
        float4 o0 = make_float4(acc[i][0] + bb0[0], acc[i][1] + bb0[1],
                                acc[i][2] + bb0[2], acc[i][3] + bb0[3]);
        float4 o1 = make_float4(acc[i][4] + bb0[4], acc[i][5] + bb0[5],
                                acc[i][6] + bb0[6], acc[i][7] + bb0[7]);
        *(float4*)(C + row * P + bn + tc * 8)     = o0;
        *(float4*)(C + row * P + bn + tc * 8 + 4) = o1;
    }
}

// ---------------- small SGEMM (layer 3, P=12), bounds-checked ----------------
#define BM 64
#define BN 64
#define BKT 16
__global__ void gemm_kernel(const float* __restrict__ X, const float* __restrict__ W,
                            const float* __restrict__ bias, float* __restrict__ C,
                            int D, int P) {
    __shared__ float As[BKT][BM];
    __shared__ float Bs[BKT][BN];
    int bm = blockIdx.x * BM;
    int bn = blockIdx.y * BN;
    int tid = threadIdx.x;
    int tr = tid >> 4, tc = tid & 15;
    float acc[4][4] = {};

    for (int k0 = 0; k0 < D; k0 += BKT) {
        for (int t = tid; t < BM * BKT; t += 256) {
            int m = t >> 4, k = t & 15;
            As[k][m] = X[(size_t)(bm + m) * D + k0 + k];
        }
        for (int t = tid; t < BKT * BN; t += 256) {
            int k = t >> 6, n = t & 63;
            int nn = bn + n;
            Bs[k][n] = (nn < P) ? W[(size_t)(k0 + k) * P + nn] : 0.f;
        }
        __syncthreads();
#pragma unroll
        for (int kk = 0; kk < BKT; kk++) {
            float4 av = *(const float4*)&As[kk][tr * 4];
            float4 bv = *(const float4*)&Bs[kk][tc * 4];
            float a[4] = {av.x, av.y, av.z, av.w};
            float bb[4] = {bv.x, bv.y, bv.z, bv.w};
#pragma unroll
            for (int i = 0; i < 4; i++)
#pragma unroll
                for (int j = 0; j < 4; j++)
                    acc[i][j] = fmaf(a[i], bb[j], acc[i][j]);
        }
        __syncthreads();
    }
#pragma unroll
    for (int i = 0; i < 4; i++) {
        int row = bm + tr * 4 + i;
#pragma unroll
        for (int j = 0; j < 4; j++) {
            int col = bn + tc * 4 + j;
            if (col < P) C[(size_t)row * P + col] = acc[i][j] + bias[col];
        }
    }
}

// ---------------- attention, c=128 layers (block per node); packed QKVS ----------------
__global__ void attn128_kernel(const float* __restrict__ pk,
                               const float* __restrict__ resid,
                               float* __restrict__ outp, int do_tanh) {
    __shared__ float sq[128];
    __shared__ float al[16];
    __shared__ int   nb[16];
    int i = blockIdx.x;
    int t = threadIdx.x;
    if (t < 16) nb[t] = g_nbr[i * 16 + t];
    sq[t] = pk[(size_t)i * 512 + t];            // Q at offset 0
    __syncthreads();

    int w = t >> 5, l = t & 31;
#pragma unroll
    for (int ee = 0; ee < 4; ee++) {
        int e = (w << 2) + ee;
        int j = nb[e];
        const float* kj = pk + (size_t)j * 512 + 128;   // K at offset 128
        float a = sq[l] * kj[l];
        a = fmaf(sq[l + 32], kj[l + 32], a);
        a = fmaf(sq[l + 64], kj[l + 64], a);
        a = fmaf(sq[l + 96], kj[l + 96], a);
#pragma unroll
        for (int o = 16; o > 0; o >>= 1) a += __shfl_xor_sync(0xffffffffu, a, o);
        if (l == 0) al[e] = a * 0.08838834764831845f;   // 1/sqrt(128)
    }
    __syncthreads();
    if (t < 32) {
        float a = (l < 16) ? al[l] : -__int_as_float(0x7f800000);
        float m = a;
#pragma unroll
        for (int o = 16; o > 0; o >>= 1) m = fmaxf(m, __shfl_xor_sync(0xffffffffu, m, o));
        float ex = (l < 16) ? expf(a - m) : 0.f;
        float sm = ex;
#pragma unroll
        for (int o = 16; o > 0; o >>= 1) sm += __shfl_xor_sync(0xffffffffu, sm, o);
        if (l < 16) al[l] = ex / sm;
    }
    __syncthreads();

    float acc = pk[(size_t)i * 512 + 384 + t];          // S at offset 384
#pragma unroll
    for (int e = 0; e < 16; e++)
        acc = fmaf(al[e], pk[(size_t)nb[e] * 512 + 256 + t], acc);  // V at 256
    if (resid) acc += resid[(size_t)i * 128 + t];
    outp[(size_t)i * 128 + t] = do_tanh ? tanhf(acc) : acc;
}

// ---------------- attention, c=3 final layer (warp per node); packed P=12 ----------------
__global__ void attn3_kernel(const float* __restrict__ pk, float* __restrict__ outp) {
    int gt = blockIdx.x * blockDim.x + threadIdx.x;
    int i = gt >> 5;
    int l = gt & 31;
    if (i >= NPTS) return;
    int j = 0;
    float a = -__int_as_float(0x7f800000);
    if (l < 16) {
        j = g_nbr[i * 16 + l];
        float qx = pk[i * 12 + 0], qy = pk[i * 12 + 1], qz = pk[i * 12 + 2];
        a = fmaf(qx, pk[j * 12 + 3], fmaf(qy, pk[j * 12 + 4], qz * pk[j * 12 + 5]))
            * 0.5773502691896258f;   // 1/sqrt(3)
    }
    float m = a;
#pragma unroll
    for (int o = 16; o > 0; o >>= 1) m = fmaxf(m, __shfl_xor_sync(0xffffffffu, m, o));
    float ex = (l < 16) ? expf(a - m) : 0.f;
    float sm = ex;
#pragma unroll
    for (int o = 16; o > 0; o >>= 1) sm += __shfl_xor_sync(0xffffffffu, sm, o);
    float wgt = ex / sm;
    float vx = 0.f, vy = 0.f, vz = 0.f;
    if (l < 16) {
        vx = wgt * pk[j * 12 + 6];
        vy = wgt * pk[j * 12 + 7];
        vz = wgt * pk[j * 12 + 8];
    }
#pragma unroll
    for (int o = 16; o > 0; o >>= 1) {
        vx += __shfl_xor_sync(0xffffffffu, vx, o);
        vy += __shfl_xor_sync(0xffffffffu, vy, o);
        vz += __shfl_xor_sync(0xffffffffu, vz, o);
    }
    if (l == 0) {
        outp[i * 3 + 0] = vx + pk[i * 12 + 9];
        outp[i * 3 + 1] = vy + pk[i * 12 + 10];
        outp[i * 3 + 2] = vz + pk[i * 12 + 11];
    }
}

// ---------------- host ----------------
extern "C" void kernel_launch(void* const* d_in, const int* in_sizes, int n_in,
                              void* d_out, int out_size) {
    const float* x = (const float*)d_in[1];
    const float* W1[4] = {(const float*)d_in[2], (const float*)d_in[4],
                          (const float*)d_in[6], (const float*)d_in[8]};
    const float* B1[4] = {(const float*)d_in[3], (const float*)d_in[5],
                          (const float*)d_in[7], (const float*)d_in[9]};
    const float* W2[4] = {(const float*)d_in[10], (const float*)d_in[12],
                          (const float*)d_in[14], (const float*)d_in[16]};
    const float* B2[4] = {(const float*)d_in[11], (const float*)d_in[13],
                          (const float*)d_in[15], (const float*)d_in[17]};
    const float* W3[4] = {(const float*)d_in[18], (const float*)d_in[20],
                          (const float*)d_in[22], (const float*)d_in[24]};
    const float* B3[4] = {(const float*)d_in[19], (const float*)d_in[21],
                          (const float*)d_in[23], (const float*)d_in[25]};
    float* out = (float*)d_out;

    float *qkvs, *h1, *h2, *Wp1, *Wp2, *Wp3, *Bp1, *Bp2, *Bp3;
    void *hist, *bbmin, *bbmax, *done;
    cudaGetSymbolAddress((void**)&qkvs, g_qkvs);
    cudaGetSymbolAddress((void**)&h1,  g_h1);
    cudaGetSymbolAddress((void**)&h2,  g_h2);
    cudaGetSymbolAddress((void**)&Wp1, g_Wp1);
    cudaGetSymbolAddress((void**)&Wp2, g_Wp2);
    cudaGetSymbolAddress((void**)&Wp3, g_Wp3);
    cudaGetSymbolAddress((void**)&Bp1, g_Bp1);
    cudaGetSymbolAddress((void**)&Bp2, g_Bp2);
    cudaGetSymbolAddress((void**)&Bp3, g_Bp3);
    cudaGetSymbolAddress(&hist,  g_hist);
    cudaGetSymbolAddress(&bbmin, g_bbmin);
    cudaGetSymbolAddress(&bbmax, g_bbmax);
    cudaGetSymbolAddress(&done,  g_done);

    // per-replay state reset (memset nodes, not kernel launches)
    cudaMemsetAsync(hist,  0x00, NCELLS * sizeof(int));
    cudaMemsetAsync(bbmin, 0xFF, 3 * sizeof(unsigned));
    cudaMemsetAsync(bbmax, 0x00, 3 * sizeof(unsigned));
    cudaMemsetAsync(done,  0x00, sizeof(unsigned));

    // slot 4 (ncu capture) = gemm128 layer-1 -> evidence for tensor-core decision
    bbox_kernel<<<64, 256>>>(x);                                            // 1
    pack_b_kernel<<<1, 128>>>(B1[0], B1[1], B1[2], B1[3], Bp1, 128);        // 2
    pack_w_kernel<<<(64 * 128 + 255) / 256, 256>>>(W1[0], W1[1], W1[2], W1[3], Wp1, 64, 128); // 3
    {
        dim3 grid(NPTS / GBM, 512 / GBN);
        gemm128_kernel<<<grid, 256>>>(x, Wp1, Bp1, qkvs, 64, 512);          // 4 <- profiled
    }
    prep_hist_kernel<<<64, 256>>>(x);                                       // 5
    scan_scatter_kernel<<<1, 1024>>>();                                     // 6
    knn_query_kernel<<<NPTS / 4, 128>>>();                                  // 7 (warp/query)

    pack_b_kernel<<<1, 128>>>(B2[0], B2[1], B2[2], B2[3], Bp2, 128);
    pack_b_kernel<<<1, 128>>>(B3[0], B3[1], B3[2], B3[3], Bp3, 3);
    pack_w_kernel<<<(128 * 128 + 255) / 256, 256>>>(W2[0], W2[1], W2[2], W2[3], Wp2, 128, 128);
    pack_w_kernel<<<(128 * 3 + 255) / 256, 256>>>(W3[0], W3[1], W3[2], W3[3], Wp3, 128, 3);

    // layer 1 attention
    attn128_kernel<<<NPTS, 128>>>(qkvs, nullptr, h1, 1);

    // layer 2
    {
        dim3 grid(NPTS / GBM, 512 / GBN);
        gemm128_kernel<<<grid, 256>>>(h1, Wp2, Bp2, qkvs, 128, 512);
    }
    attn128_kernel<<<NPTS, 128>>>(qkvs, h1, h2, 1);

    // layer 3
    {
        dim3 grid(NPTS / BM, 1);
        gemm_kernel<<<grid, 256>>>(h2, Wp3, Bp3, qkvs, 128, 12);
    }
    attn3_kernel<<<(NPTS * 32) / 128, 128>>>(qkvs, out);
}